// round 16
// baseline (speedup 1.0000x reference)
#include <cuda_runtime.h>
#include <cuda_bf16.h>
#include <cstdint>

using bf16 = __nv_bfloat16;

#define B_  8
#define C_  512
#define T_  2048
#define CQ_ 64
#define MQKV 640

// ---------------------------------------------------------------------------
// Device-global scratch
// ---------------------------------------------------------------------------
__device__ bf16  g_xb  [B_ * C_ * T_];
__device__ bf16  g_wall[MQKV * C_];
__device__ float g_ball[MQKV];
__device__ bf16  g_qkv [(size_t)B_ * MQKV * T_];
__device__ bf16  g_p   [(size_t)B_ * T_ * T_];
__device__ float g_rs  [B_ * 8 * T_];

// ---------------------------------------------------------------------------
// PTX helpers
// ---------------------------------------------------------------------------
__device__ __forceinline__ uint32_t cvta_s(const void* p) {
    return (uint32_t)__cvta_generic_to_shared(p);
}
__device__ __forceinline__ void ldsm_x4(uint32_t* r, uint32_t a) {
    asm volatile("ldmatrix.sync.aligned.m8n8.x4.shared.b16 {%0,%1,%2,%3},[%4];"
                 : "=r"(r[0]), "=r"(r[1]), "=r"(r[2]), "=r"(r[3]) : "r"(a));
}
__device__ __forceinline__ void ldsm_x4t(uint32_t* r, uint32_t a) {
    asm volatile("ldmatrix.sync.aligned.m8n8.x4.trans.shared.b16 {%0,%1,%2,%3},[%4];"
                 : "=r"(r[0]), "=r"(r[1]), "=r"(r[2]), "=r"(r[3]) : "r"(a));
}
__device__ __forceinline__ void mma_bf16(float* c, const uint32_t* a, const uint32_t* b) {
    asm volatile("mma.sync.aligned.m16n8k16.row.col.f32.bf16.bf16.f32 "
                 "{%0,%1,%2,%3},{%4,%5,%6,%7},{%8,%9},{%0,%1,%2,%3};"
                 : "+f"(c[0]), "+f"(c[1]), "+f"(c[2]), "+f"(c[3])
                 : "r"(a[0]), "r"(a[1]), "r"(a[2]), "r"(a[3]), "r"(b[0]), "r"(b[1]));
}
__device__ __forceinline__ void cp16(uint32_t dst, const void* src) {
    asm volatile("cp.async.ca.shared.global [%0], [%1], 16;" :: "r"(dst), "l"(src));
}
#define CP_COMMIT() asm volatile("cp.async.commit_group;" ::: "memory")
#define CP_WAIT(n)  asm volatile("cp.async.wait_group %0;" :: "n"(n) : "memory")

// ---------------------------------------------------------------------------
// Converts (validated round 11)
// ---------------------------------------------------------------------------
__device__ __forceinline__ void cvt4(const float* in, bf16* out, int i) {
    float4 v = *reinterpret_cast<const float4*>(in + (size_t)i * 4);
    __nv_bfloat162 lo = __floats2bfloat162_rn(v.x, v.y);
    __nv_bfloat162 hi = __floats2bfloat162_rn(v.z, v.w);
    uint2 pk;
    pk.x = *reinterpret_cast<uint32_t*>(&lo);
    pk.y = *reinterpret_cast<uint32_t*>(&hi);
    *reinterpret_cast<uint2*>(out + (size_t)i * 4) = pk;
}
#define NX4  ((B_ * C_ * T_) / 4)
#define NQ4  ((CQ_ * C_) / 4)
#define NV4  ((C_ * C_) / 4)
#define NTOT (NX4 + 2 * NQ4 + NV4 + MQKV)

__global__ void f2b_all(const float* __restrict__ x,  bf16* __restrict__ xb,
                        const float* __restrict__ wq, const float* __restrict__ wk,
                        const float* __restrict__ wv, bf16* __restrict__ wall,
                        const float* __restrict__ bq, const float* __restrict__ bk,
                        const float* __restrict__ bv, float* __restrict__ ball)
{
    int i = blockIdx.x * blockDim.x + threadIdx.x;
    if (i < NX4)                       { cvt4(x, xb, i); return; }
    i -= NX4;
    if (i < NQ4)                       { cvt4(wq, wall, i); return; }
    i -= NQ4;
    if (i < NQ4)                       { cvt4(wk, wall + CQ_ * C_, i); return; }
    i -= NQ4;
    if (i < NV4)                       { cvt4(wv, wall + 2 * CQ_ * C_, i); return; }
    i -= NV4;
    if (i < MQKV) {
        float v;
        if (i < 64)       v = bq[i];
        else if (i < 128) v = bk[i - 64];
        else              v = bv[i - 128];
        ball[i] = v;
    }
}

// ---------------------------------------------------------------------------
// Stacked QKV projection (validated round 11) + batch offset
// ---------------------------------------------------------------------------
#define PJ_A0 0u
#define PJ_A1 18432u
#define PJ_B0 36864u
#define PJ_B1 54272u
#define PJ_SMEM 71680u

__device__ __forceinline__ void pj_issue_chunk(const bf16* W, const bf16* Xb,
                                               int m0, int n0, int kc,
                                               uint32_t sb, int buf, int tid)
{
    const uint32_t aoff = buf ? PJ_A1 : PJ_A0;
    const uint32_t boff = buf ? PJ_B1 : PJ_B0;
    #pragma unroll
    for (int j = 0; j < 4; j++) {
        int u = tid + j * 256;
        int row = u >> 3, c16 = u & 7;
        cp16(sb + aoff + (uint32_t)(row * 144 + c16 * 16),
             &W[(size_t)(m0 + row) * C_ + kc + c16 * 8]);
    }
    #pragma unroll
    for (int j = 0; j < 4; j++) {
        int u = tid + j * 256;
        int row = u >> 4, c16 = u & 15;
        cp16(sb + boff + (uint32_t)(row * 272 + c16 * 16),
             &Xb[(size_t)(kc + row) * T_ + n0 + c16 * 8]);
    }
    CP_COMMIT();
}

__global__ void __launch_bounds__(256, 2)
proj_stk(const bf16* __restrict__ Wall, const float* __restrict__ ball,
         const bf16* __restrict__ X, bf16* __restrict__ QKV, int bofs)
{
    extern __shared__ __align__(128) char smem[];
    const uint32_t sb = cvta_s(smem);

    const int b  = blockIdx.z + bofs;
    const int n0 = blockIdx.x * 128;
    const int m0 = blockIdx.y * 128;
    const bf16* Xb = X + (size_t)b * C_ * T_;
    bf16* Ob = QKV + (size_t)b * MQKV * T_;

    const int tid  = threadIdx.x;
    const int lane = tid & 31;
    const int w    = tid >> 5;
    const int wm   = (w >> 2) * 64;
    const int wn   = (w & 3) * 32;

    float acc[4][4][4] = {};

    pj_issue_chunk(Wall, Xb, m0, n0, 0,  sb, 0, tid);
    pj_issue_chunk(Wall, Xb, m0, n0, 64, sb, 1, tid);

    #pragma unroll 1
    for (int ch = 0; ch < 8; ch++) {
        const int buf = ch & 1;
        if (ch < 7) { CP_WAIT(1); } else { CP_WAIT(0); }
        __syncthreads();

        const bf16* sA = reinterpret_cast<const bf16*>(smem + (buf ? PJ_A1 : PJ_A0));
        const bf16* sB = reinterpret_cast<const bf16*>(smem + (buf ? PJ_B1 : PJ_B0));

        #pragma unroll
        for (int kk = 0; kk < 64; kk += 16) {
            uint32_t af[4][4], bf_[4][2];
            #pragma unroll
            for (int mi = 0; mi < 4; mi++) {
                uint32_t a = cvta_s(&sA[(wm + mi * 16 + (lane & 15)) * 72 + kk + (lane >> 4) * 8]);
                ldsm_x4(af[mi], a);
            }
            #pragma unroll
            for (int p = 0; p < 2; p++) {
                uint32_t tmp[4];
                uint32_t a = cvta_s(&sB[(kk + ((lane >> 3) & 1) * 8 + (lane & 7)) * 136 +
                                        wn + p * 16 + (lane >> 4) * 8]);
                ldsm_x4t(tmp, a);
                bf_[2 * p][0] = tmp[0]; bf_[2 * p][1] = tmp[1];
                bf_[2 * p + 1][0] = tmp[2]; bf_[2 * p + 1][1] = tmp[3];
            }
            #pragma unroll
            for (int mi = 0; mi < 4; mi++)
                #pragma unroll
                for (int ni = 0; ni < 4; ni++)
                    mma_bf16(acc[mi][ni], af[mi], bf_[ni]);
        }
        __syncthreads();

        if (ch + 2 < 8)
            pj_issue_chunk(Wall, Xb, m0, n0, (ch + 2) * 64, sb, buf, tid);
    }

    #pragma unroll
    for (int mi = 0; mi < 4; mi++) {
        int grow = m0 + wm + mi * 16 + (lane >> 2);
        float bv0 = ball[grow];
        float bv1 = ball[grow + 8];
        #pragma unroll
        for (int ni = 0; ni < 4; ni++) {
            int gcol = n0 + wn + ni * 8 + (lane & 3) * 2;
            __nv_bfloat162 v0 = __floats2bfloat162_rn(acc[mi][ni][0] + bv0, acc[mi][ni][1] + bv0);
            __nv_bfloat162 v1 = __floats2bfloat162_rn(acc[mi][ni][2] + bv1, acc[mi][ni][3] + bv1);
            *reinterpret_cast<__nv_bfloat162*>(&Ob[(size_t)grow * T_ + gcol]) = v0;
            *reinterpret_cast<__nv_bfloat162*>(&Ob[(size_t)(grow + 8) * T_ + gcol]) = v1;
        }
    }
}

// ---------------------------------------------------------------------------
// Scores + exp (validated round 10/11) + batch offset
// ---------------------------------------------------------------------------
#define SC_Q    0u
#define SC_K0   17408u
#define SC_K1   34816u
#define SC_STG  52224u
#define SC_RED  87040u
#define SC_SMEM 89088u

__global__ void __launch_bounds__(256, 2)
score_exp4(const bf16* __restrict__ QKV, bf16* __restrict__ P,
           float* __restrict__ partial, int bofs)
{
    extern __shared__ __align__(16) char sm[];
    const uint32_t sb = cvta_s(sm);
    bf16*  sQ  = reinterpret_cast<bf16*>(sm + SC_Q);
    bf16*  stg = reinterpret_cast<bf16*>(sm + SC_STG);
    float* red = reinterpret_cast<float*>(sm + SC_RED);

    const int b   = blockIdx.z + bofs;
    const int s0g = blockIdx.x * 256;
    const int t0  = blockIdx.y * 128;
    const bf16* Qb = QKV + (size_t)b * MQKV * T_;
    const bf16* Kb = Qb + (size_t)CQ_ * T_;

    const int tid  = threadIdx.x;
    const int lane = tid & 31;
    const int w    = tid >> 5;
    const int wm   = (w >> 2) * 64;
    const int wn   = (w & 3) * 32;

    #pragma unroll
    for (int j = 0; j < 4; j++) {
        int u = tid + j * 256;
        int r = u >> 4, c16 = u & 15;
        cp16(sb + SC_Q + (uint32_t)(r * 272 + c16 * 16),
             &Qb[(size_t)r * T_ + t0 + c16 * 8]);
        cp16(sb + SC_K0 + (uint32_t)(r * 272 + c16 * 16),
             &Kb[(size_t)r * T_ + s0g + c16 * 8]);
    }
    CP_COMMIT();
    #pragma unroll
    for (int j = 0; j < 4; j++) {
        int u = tid + j * 256;
        int r = u >> 4, c16 = u & 15;
        cp16(sb + SC_K1 + (uint32_t)(r * 272 + c16 * 16),
             &Kb[(size_t)r * T_ + s0g + 128 + c16 * 8]);
    }
    CP_COMMIT();

    float rs[4][2] = {};
    bf16* Pb = P + (size_t)b * T_ * T_;

    #pragma unroll 1
    for (int it = 0; it < 2; it++) {
        if (it == 0) { CP_WAIT(1); } else { CP_WAIT(0); }
        __syncthreads();

        const bf16* sK = reinterpret_cast<const bf16*>(sm + (it ? SC_K1 : SC_K0));

        float acc[4][4][4] = {};
        #pragma unroll
        for (int kk = 0; kk < 64; kk += 16) {
            uint32_t af[4][4], bf_[4][2];
            const int g = lane >> 3;
            #pragma unroll
            for (int mi = 0; mi < 4; mi++) {
                uint32_t a = cvta_s(&sQ[(kk + (g >> 1) * 8 + (lane & 7)) * 136 +
                                        wm + mi * 16 + (g & 1) * 8]);
                ldsm_x4t(af[mi], a);
            }
            #pragma unroll
            for (int p = 0; p < 2; p++) {
                uint32_t tmp[4];
                uint32_t a = cvta_s(&sK[(kk + ((lane >> 3) & 1) * 8 + (lane & 7)) * 136 +
                                        wn + p * 16 + (lane >> 4) * 8]);
                ldsm_x4t(tmp, a);
                bf_[2 * p][0] = tmp[0]; bf_[2 * p][1] = tmp[1];
                bf_[2 * p + 1][0] = tmp[2]; bf_[2 * p + 1][1] = tmp[3];
            }
            #pragma unroll
            for (int mi = 0; mi < 4; mi++)
                #pragma unroll
                for (int ni = 0; ni < 4; ni++)
                    mma_bf16(acc[mi][ni], af[mi], bf_[ni]);
        }

        #pragma unroll
        for (int mi = 0; mi < 4; mi++) {
            int r0 = wm + mi * 16 + (lane >> 2);
            #pragma unroll
            for (int ni = 0; ni < 4; ni++) {
                float p0 = __expf(acc[mi][ni][0]);
                float p1 = __expf(acc[mi][ni][1]);
                float p2 = __expf(acc[mi][ni][2]);
                float p3 = __expf(acc[mi][ni][3]);
                rs[mi][0] += p0 + p1;
                rs[mi][1] += p2 + p3;
                int cc = wn + ni * 8 + (lane & 3) * 2;
                __nv_bfloat162 lo = __floats2bfloat162_rn(p0, p1);
                __nv_bfloat162 hi = __floats2bfloat162_rn(p2, p3);
                *reinterpret_cast<__nv_bfloat162*>(&stg[r0 * 136 + cc]) = lo;
                *reinterpret_cast<__nv_bfloat162*>(&stg[(r0 + 8) * 136 + cc]) = hi;
            }
        }
        __syncthreads();

        const int sg = s0g + it * 128;
        #pragma unroll
        for (int j = 0; j < 8; j++) {
            int u = tid + j * 256;
            int row = u >> 4, c = (u & 15) * 8;
            *reinterpret_cast<uint4*>(&Pb[(size_t)(t0 + row) * T_ + sg + c]) =
                *reinterpret_cast<const uint4*>(&stg[row * 136 + c]);
        }
    }

    #pragma unroll
    for (int mi = 0; mi < 4; mi++)
        #pragma unroll
        for (int h = 0; h < 2; h++) {
            float v = rs[mi][h];
            v += __shfl_xor_sync(0xffffffffu, v, 1);
            v += __shfl_xor_sync(0xffffffffu, v, 2);
            if ((lane & 3) == 0)
                red[(w & 3) * 128 + wm + mi * 16 + h * 8 + (lane >> 2)] = v;
        }
    __syncthreads();
    if (tid < 128) {
        float tot = red[tid] + red[128 + tid] + red[256 + tid] + red[384 + tid];
        partial[((size_t)b * 8 + blockIdx.x) * T_ + t0 + tid] = tot;
    }
}

// ---------------------------------------------------------------------------
// Output GEMM (round-12 winner) + batch offset
// ---------------------------------------------------------------------------
#define OA0 0u
#define OA1 18432u
#define OB0 36864u
#define OB1 55296u
#define OINV 73728u
#define OUT_SMEM 74240u

__device__ __forceinline__ void out_issue_chunk(const bf16* Vb, const bf16* Pb,
                                                int m0, int n0, int kc,
                                                uint32_t sb, int buf, int tid)
{
    const uint32_t aoff = buf ? OA1 : OA0;
    const uint32_t boff = buf ? OB1 : OB0;
    #pragma unroll
    for (int j = 0; j < 8; j++) {
        int u = tid + j * 128;
        int row = u >> 3, c16 = u & 7;
        cp16(sb + aoff + (uint32_t)(row * 144 + c16 * 16),
             &Vb[(size_t)(m0 + row) * T_ + kc + c16 * 8]);
    }
    #pragma unroll
    for (int j = 0; j < 8; j++) {
        int u = tid + j * 128;
        int row = u >> 3, c16 = u & 7;
        cp16(sb + boff + (uint32_t)(row * 144 + c16 * 16),
             &Pb[(size_t)(n0 + row) * T_ + kc + c16 * 8]);
    }
    CP_COMMIT();
}

__global__ void __launch_bounds__(128, 2)
out_mma5(const bf16* __restrict__ QKV, const bf16* __restrict__ P,
         const float* __restrict__ rsum, const float* __restrict__ x,
         const float* __restrict__ gamma, float* __restrict__ O, int bofs)
{
    extern __shared__ __align__(128) char smem[];
    const uint32_t sb = cvta_s(smem);
    float* sInv = reinterpret_cast<float*>(smem + OINV);

    const int b  = blockIdx.z + bofs;
    const int n0 = blockIdx.x * 128;   // t
    const int m0 = blockIdx.y * 128;   // c
    const bf16* Vb = QKV + (size_t)b * MQKV * T_ + (size_t)(2 * CQ_) * T_;
    const bf16* Pb = P + (size_t)b * T_ * T_;

    const int tid  = threadIdx.x;
    const int lane = tid & 31;
    const int w    = tid >> 5;
    const int wm   = (w >> 1) * 64;
    const int wn   = (w & 1) * 64;

    {
        const float* p = rsum + (size_t)b * 8 * T_ + n0 + tid;
        float s = 0.0f;
        #pragma unroll
        for (int j = 0; j < 8; j++) s += p[j * T_];
        sInv[tid] = 1.0f / s;
    }

    float acc[4][8][4] = {};

    out_issue_chunk(Vb, Pb, m0, n0, 0,  sb, 0, tid);
    out_issue_chunk(Vb, Pb, m0, n0, 64, sb, 1, tid);

    #pragma unroll 1
    for (int ch = 0; ch < 32; ch++) {
        const int buf = ch & 1;
        if (ch < 31) { CP_WAIT(1); } else { CP_WAIT(0); }
        __syncthreads();

        const bf16* sA = reinterpret_cast<const bf16*>(smem + (buf ? OA1 : OA0));
        const bf16* sB = reinterpret_cast<const bf16*>(smem + (buf ? OB1 : OB0));

        #pragma unroll
        for (int kk = 0; kk < 64; kk += 16) {
            uint32_t af[4][4], bf_[8][2];
            #pragma unroll
            for (int mi = 0; mi < 4; mi++) {
                uint32_t a = cvta_s(&sA[(wm + mi * 16 + (lane & 15)) * 72 + kk + (lane >> 4) * 8]);
                ldsm_x4(af[mi], a);
            }
            #pragma unroll
            for (int p = 0; p < 4; p++) {
                uint32_t tmp[4];
                uint32_t a = cvta_s(&sB[(wn + p * 16 + (lane >> 4) * 8 + (lane & 7)) * 72 +
                                        kk + ((lane >> 3) & 1) * 8]);
                ldsm_x4(tmp, a);
                bf_[2 * p][0] = tmp[0]; bf_[2 * p][1] = tmp[1];
                bf_[2 * p + 1][0] = tmp[2]; bf_[2 * p + 1][1] = tmp[3];
            }
            #pragma unroll
            for (int mi = 0; mi < 4; mi++)
                #pragma unroll
                for (int ni = 0; ni < 8; ni++)
                    mma_bf16(acc[mi][ni], af[mi], bf_[ni]);
        }
        __syncthreads();

        if (ch + 2 < 32)
            out_issue_chunk(Vb, Pb, m0, n0, (ch + 2) * 64, sb, buf, tid);
    }

    const float g = gamma[0];
    #pragma unroll
    for (int mi = 0; mi < 4; mi++) {
        int grow = m0 + wm + mi * 16 + (lane >> 2);
        #pragma unroll
        for (int ni = 0; ni < 8; ni++) {
            int lc = wn + ni * 8 + (lane & 3) * 2;
            int gcol = n0 + lc;
            float2 iv = *reinterpret_cast<const float2*>(&sInv[lc]);
            size_t i0 = (size_t)b * C_ * T_ + (size_t)grow * T_ + gcol;
            size_t i1 = (size_t)b * C_ * T_ + (size_t)(grow + 8) * T_ + gcol;
            float2 x0 = *reinterpret_cast<const float2*>(&x[i0]);
            float2 x1 = *reinterpret_cast<const float2*>(&x[i1]);
            *reinterpret_cast<float2*>(&O[i0]) =
                make_float2(g * acc[mi][ni][0] * iv.x + x0.x, g * acc[mi][ni][1] * iv.y + x0.y);
            *reinterpret_cast<float2*>(&O[i1]) =
                make_float2(g * acc[mi][ni][2] * iv.x + x1.x, g * acc[mi][ni][3] * iv.y + x1.y);
        }
    }
}

// ---------------------------------------------------------------------------
// Launch: two-stream fork/join using the built-in per-thread stream.
// No stream/event device allocations: cudaStreamPerThread is a handle;
// events are created with DisableTiming (host-side sync objects).
// ---------------------------------------------------------------------------
extern "C" void kernel_launch(void* const* d_in, const int* in_sizes, int n_in,
                              void* d_out, int out_size)
{
    const float* x     = (const float*)d_in[0];
    const float* wq    = (const float*)d_in[1];
    const float* bq    = (const float*)d_in[2];
    const float* wk    = (const float*)d_in[3];
    const float* bk    = (const float*)d_in[4];
    const float* wv    = (const float*)d_in[5];
    const float* bv    = (const float*)d_in[6];
    const float* gamma = (const float*)d_in[7];
    float* out = (float*)d_out;

    bf16 *xb, *wall, *qkv, *pb;
    float *ball, *rs;
    cudaGetSymbolAddress((void**)&xb,   g_xb);
    cudaGetSymbolAddress((void**)&wall, g_wall);
    cudaGetSymbolAddress((void**)&ball, g_ball);
    cudaGetSymbolAddress((void**)&qkv,  g_qkv);
    cudaGetSymbolAddress((void**)&pb,   g_p);
    cudaGetSymbolAddress((void**)&rs,   g_rs);

    static bool init_done = false;
    static cudaEvent_t ev_fork, ev_join;
    if (!init_done) {
        cudaFuncSetAttribute(proj_stk,   cudaFuncAttributeMaxDynamicSharedMemorySize, PJ_SMEM);
        cudaFuncSetAttribute(score_exp4, cudaFuncAttributeMaxDynamicSharedMemorySize, SC_SMEM);
        cudaFuncSetAttribute(out_mma5,   cudaFuncAttributeMaxDynamicSharedMemorySize, OUT_SMEM);
        cudaEventCreateWithFlags(&ev_fork, cudaEventDisableTiming);
        cudaEventCreateWithFlags(&ev_join, cudaEventDisableTiming);
        init_done = true;
    }

    cudaStream_t s2 = cudaStreamPerThread;

    // converts on the capture (legacy) stream
    f2b_all<<<(NTOT + 255) / 256, 256>>>(x, xb, wq, wk, wv, wall, bq, bk, bv, ball);
    cudaEventRecord(ev_fork, 0);
    cudaStreamWaitEvent(s2, ev_fork, 0);

    // half 1 (batches 0-3) on the legacy stream
    proj_stk  <<<dim3(T_ / 128, MQKV / 128, 4), 256, PJ_SMEM>>>(wall, ball, xb, qkv, 0);
    score_exp4<<<dim3(T_ / 256, T_ / 128, 4), 256, SC_SMEM>>>(qkv, pb, rs, 0);
    out_mma5  <<<dim3(T_ / 128, C_ / 128, 4), 128, OUT_SMEM>>>(qkv, pb, rs, x, gamma, out, 0);

    // half 2 (batches 4-7) on the per-thread stream
    proj_stk  <<<dim3(T_ / 128, MQKV / 128, 4), 256, PJ_SMEM, s2>>>(wall, ball, xb, qkv, 4);
    score_exp4<<<dim3(T_ / 256, T_ / 128, 4), 256, SC_SMEM, s2>>>(qkv, pb, rs, 4);
    out_mma5  <<<dim3(T_ / 128, C_ / 128, 4), 128, OUT_SMEM, s2>>>(qkv, pb, rs, x, gamma, out, 4);

    cudaEventRecord(ev_join, s2);
    cudaStreamWaitEvent(0, ev_join, 0);
}

// round 17
// speedup vs baseline: 1.0976x; 1.0976x over previous
#include <cuda_runtime.h>
#include <cuda_bf16.h>
#include <cstdint>

using bf16 = __nv_bfloat16;

#define B_  8
#define C_  512
#define T_  2048
#define CQ_ 64
#define MQKV 640

// ---------------------------------------------------------------------------
// Device-global scratch
// ---------------------------------------------------------------------------
__device__ bf16  g_xb  [B_ * C_ * T_];
__device__ bf16  g_wall[MQKV * C_];
__device__ float g_ball[MQKV];
__device__ bf16  g_qkv [(size_t)B_ * MQKV * T_];
__device__ bf16  g_p   [(size_t)B_ * T_ * T_];
__device__ float g_rs  [B_ * 4 * T_];            // 4 s-slices per batch now

// ---------------------------------------------------------------------------
// PTX helpers
// ---------------------------------------------------------------------------
__device__ __forceinline__ uint32_t cvta_s(const void* p) {
    return (uint32_t)__cvta_generic_to_shared(p);
}
__device__ __forceinline__ void ldsm_x4(uint32_t* r, uint32_t a) {
    asm volatile("ldmatrix.sync.aligned.m8n8.x4.shared.b16 {%0,%1,%2,%3},[%4];"
                 : "=r"(r[0]), "=r"(r[1]), "=r"(r[2]), "=r"(r[3]) : "r"(a));
}
__device__ __forceinline__ void ldsm_x4t(uint32_t* r, uint32_t a) {
    asm volatile("ldmatrix.sync.aligned.m8n8.x4.trans.shared.b16 {%0,%1,%2,%3},[%4];"
                 : "=r"(r[0]), "=r"(r[1]), "=r"(r[2]), "=r"(r[3]) : "r"(a));
}
__device__ __forceinline__ void mma_bf16(float* c, const uint32_t* a, const uint32_t* b) {
    asm volatile("mma.sync.aligned.m16n8k16.row.col.f32.bf16.bf16.f32 "
                 "{%0,%1,%2,%3},{%4,%5,%6,%7},{%8,%9},{%0,%1,%2,%3};"
                 : "+f"(c[0]), "+f"(c[1]), "+f"(c[2]), "+f"(c[3])
                 : "r"(a[0]), "r"(a[1]), "r"(a[2]), "r"(a[3]), "r"(b[0]), "r"(b[1]));
}
__device__ __forceinline__ void cp16(uint32_t dst, const void* src) {
    asm volatile("cp.async.ca.shared.global [%0], [%1], 16;" :: "r"(dst), "l"(src));
}
__device__ __forceinline__ void cp16cg(uint32_t dst, const void* src) {
    asm volatile("cp.async.cg.shared.global [%0], [%1], 16;" :: "r"(dst), "l"(src));
}
#define CP_COMMIT() asm volatile("cp.async.commit_group;" ::: "memory")
#define CP_WAIT(n)  asm volatile("cp.async.wait_group %0;" :: "n"(n) : "memory")

// ---------------------------------------------------------------------------
// Converts (validated round 11)
// ---------------------------------------------------------------------------
__device__ __forceinline__ void cvt4(const float* in, bf16* out, int i) {
    float4 v = *reinterpret_cast<const float4*>(in + (size_t)i * 4);
    __nv_bfloat162 lo = __floats2bfloat162_rn(v.x, v.y);
    __nv_bfloat162 hi = __floats2bfloat162_rn(v.z, v.w);
    uint2 pk;
    pk.x = *reinterpret_cast<uint32_t*>(&lo);
    pk.y = *reinterpret_cast<uint32_t*>(&hi);
    *reinterpret_cast<uint2*>(out + (size_t)i * 4) = pk;
}
#define NX4  ((B_ * C_ * T_) / 4)
#define NQ4  ((CQ_ * C_) / 4)
#define NV4  ((C_ * C_) / 4)
#define NTOT (NX4 + 2 * NQ4 + NV4 + MQKV)

__global__ void f2b_all(const float* __restrict__ x,  bf16* __restrict__ xb,
                        const float* __restrict__ wq, const float* __restrict__ wk,
                        const float* __restrict__ wv, bf16* __restrict__ wall,
                        const float* __restrict__ bq, const float* __restrict__ bk,
                        const float* __restrict__ bv, float* __restrict__ ball)
{
    int i = blockIdx.x * blockDim.x + threadIdx.x;
    if (i < NX4)                       { cvt4(x, xb, i); return; }
    i -= NX4;
    if (i < NQ4)                       { cvt4(wq, wall, i); return; }
    i -= NQ4;
    if (i < NQ4)                       { cvt4(wk, wall + CQ_ * C_, i); return; }
    i -= NQ4;
    if (i < NV4)                       { cvt4(wv, wall + 2 * CQ_ * C_, i); return; }
    i -= NV4;
    if (i < MQKV) {
        float v;
        if (i < 64)       v = bq[i];
        else if (i < 128) v = bk[i - 64];
        else              v = bv[i - 128];
        ball[i] = v;
    }
}

// ---------------------------------------------------------------------------
// Stacked QKV projection (validated round 11)
// ---------------------------------------------------------------------------
#define PJ_A0 0u
#define PJ_A1 18432u
#define PJ_B0 36864u
#define PJ_B1 54272u
#define PJ_SMEM 71680u

__device__ __forceinline__ void pj_issue_chunk(const bf16* W, const bf16* Xb,
                                               int m0, int n0, int kc,
                                               uint32_t sb, int buf, int tid)
{
    const uint32_t aoff = buf ? PJ_A1 : PJ_A0;
    const uint32_t boff = buf ? PJ_B1 : PJ_B0;
    #pragma unroll
    for (int j = 0; j < 4; j++) {
        int u = tid + j * 256;
        int row = u >> 3, c16 = u & 7;
        cp16(sb + aoff + (uint32_t)(row * 144 + c16 * 16),
             &W[(size_t)(m0 + row) * C_ + kc + c16 * 8]);
    }
    #pragma unroll
    for (int j = 0; j < 4; j++) {
        int u = tid + j * 256;
        int row = u >> 4, c16 = u & 15;
        cp16(sb + boff + (uint32_t)(row * 272 + c16 * 16),
             &Xb[(size_t)(kc + row) * T_ + n0 + c16 * 8]);
    }
    CP_COMMIT();
}

__global__ void __launch_bounds__(256, 2)
proj_stk(const bf16* __restrict__ Wall, const float* __restrict__ ball,
         const bf16* __restrict__ X, bf16* __restrict__ QKV)
{
    extern __shared__ __align__(128) char smem[];
    const uint32_t sb = cvta_s(smem);

    const int b  = blockIdx.z;
    const int n0 = blockIdx.x * 128;
    const int m0 = blockIdx.y * 128;
    const bf16* Xb = X + (size_t)b * C_ * T_;
    bf16* Ob = QKV + (size_t)b * MQKV * T_;

    const int tid  = threadIdx.x;
    const int lane = tid & 31;
    const int w    = tid >> 5;
    const int wm   = (w >> 2) * 64;
    const int wn   = (w & 3) * 32;

    float acc[4][4][4] = {};

    pj_issue_chunk(Wall, Xb, m0, n0, 0,  sb, 0, tid);
    pj_issue_chunk(Wall, Xb, m0, n0, 64, sb, 1, tid);

    #pragma unroll 1
    for (int ch = 0; ch < 8; ch++) {
        const int buf = ch & 1;
        if (ch < 7) { CP_WAIT(1); } else { CP_WAIT(0); }
        __syncthreads();

        const bf16* sA = reinterpret_cast<const bf16*>(smem + (buf ? PJ_A1 : PJ_A0));
        const bf16* sB = reinterpret_cast<const bf16*>(smem + (buf ? PJ_B1 : PJ_B0));

        #pragma unroll
        for (int kk = 0; kk < 64; kk += 16) {
            uint32_t af[4][4], bf_[4][2];
            #pragma unroll
            for (int mi = 0; mi < 4; mi++) {
                uint32_t a = cvta_s(&sA[(wm + mi * 16 + (lane & 15)) * 72 + kk + (lane >> 4) * 8]);
                ldsm_x4(af[mi], a);
            }
            #pragma unroll
            for (int p = 0; p < 2; p++) {
                uint32_t tmp[4];
                uint32_t a = cvta_s(&sB[(kk + ((lane >> 3) & 1) * 8 + (lane & 7)) * 136 +
                                        wn + p * 16 + (lane >> 4) * 8]);
                ldsm_x4t(tmp, a);
                bf_[2 * p][0] = tmp[0]; bf_[2 * p][1] = tmp[1];
                bf_[2 * p + 1][0] = tmp[2]; bf_[2 * p + 1][1] = tmp[3];
            }
            #pragma unroll
            for (int mi = 0; mi < 4; mi++)
                #pragma unroll
                for (int ni = 0; ni < 4; ni++)
                    mma_bf16(acc[mi][ni], af[mi], bf_[ni]);
        }
        __syncthreads();

        if (ch + 2 < 8)
            pj_issue_chunk(Wall, Xb, m0, n0, (ch + 2) * 64, sb, buf, tid);
    }

    #pragma unroll
    for (int mi = 0; mi < 4; mi++) {
        int grow = m0 + wm + mi * 16 + (lane >> 2);
        float bv0 = ball[grow];
        float bv1 = ball[grow + 8];
        #pragma unroll
        for (int ni = 0; ni < 4; ni++) {
            int gcol = n0 + wn + ni * 8 + (lane & 3) * 2;
            __nv_bfloat162 v0 = __floats2bfloat162_rn(acc[mi][ni][0] + bv0, acc[mi][ni][1] + bv0);
            __nv_bfloat162 v1 = __floats2bfloat162_rn(acc[mi][ni][2] + bv1, acc[mi][ni][3] + bv1);
            *reinterpret_cast<__nv_bfloat162*>(&Ob[(size_t)grow * T_ + gcol]) = v0;
            *reinterpret_cast<__nv_bfloat162*>(&Ob[(size_t)(grow + 8) * T_ + gcol]) = v1;
        }
    }
}

// ---------------------------------------------------------------------------
// Scores + exp v6: block = 128(t) x 512(s) — FOUR s-tiles, Q loaded once,
// double-buffered K with cp.async (prefetch depth 2).
// smem: sQ 17408 | sK0 17408 | sK1 17408 | stg 34816 | red 2048 = 89088
// ---------------------------------------------------------------------------
#define SC_Q    0u
#define SC_K0   17408u
#define SC_K1   34816u
#define SC_STG  52224u
#define SC_RED  87040u
#define SC_SMEM 89088u
#define SC_TILES 4

__global__ void __launch_bounds__(256, 2)
score_exp6(const bf16* __restrict__ QKV, bf16* __restrict__ P,
           float* __restrict__ partial)
{
    extern __shared__ __align__(16) char sm[];
    const uint32_t sb = cvta_s(sm);
    bf16*  sQ  = reinterpret_cast<bf16*>(sm + SC_Q);
    bf16*  stg = reinterpret_cast<bf16*>(sm + SC_STG);
    float* red = reinterpret_cast<float*>(sm + SC_RED);

    const int b   = blockIdx.z;
    const int s0g = blockIdx.x * (128 * SC_TILES);
    const int t0  = blockIdx.y * 128;
    const bf16* Qb = QKV + (size_t)b * MQKV * T_;
    const bf16* Kb = Qb + (size_t)CQ_ * T_;

    const int tid  = threadIdx.x;
    const int lane = tid & 31;
    const int w    = tid >> 5;
    const int wm   = (w >> 2) * 64;
    const int wn   = (w & 3) * 32;

    // prologue: group0 = Q + K tile0, group1 = K tile1
    #pragma unroll
    for (int j = 0; j < 4; j++) {
        int u = tid + j * 256;
        int r = u >> 4, c16 = u & 15;
        cp16cg(sb + SC_Q + (uint32_t)(r * 272 + c16 * 16),
               &Qb[(size_t)r * T_ + t0 + c16 * 8]);
        cp16cg(sb + SC_K0 + (uint32_t)(r * 272 + c16 * 16),
               &Kb[(size_t)r * T_ + s0g + c16 * 8]);
    }
    CP_COMMIT();
    #pragma unroll
    for (int j = 0; j < 4; j++) {
        int u = tid + j * 256;
        int r = u >> 4, c16 = u & 15;
        cp16cg(sb + SC_K1 + (uint32_t)(r * 272 + c16 * 16),
               &Kb[(size_t)r * T_ + s0g + 128 + c16 * 8]);
    }
    CP_COMMIT();

    float rs[4][2] = {};
    bf16* Pb = P + (size_t)b * T_ * T_;

    #pragma unroll 1
    for (int it = 0; it < SC_TILES; it++) {
        if (it < SC_TILES - 1) { CP_WAIT(1); } else { CP_WAIT(0); }
        __syncthreads();   // K[it&1] ready; all warps past previous iteration

        const bf16* sK = reinterpret_cast<const bf16*>(sm + ((it & 1) ? SC_K1 : SC_K0));

        float acc[4][4][4] = {};
        #pragma unroll
        for (int kk = 0; kk < 64; kk += 16) {
            uint32_t af[4][4], bf_[4][2];
            const int g = lane >> 3;
            #pragma unroll
            for (int mi = 0; mi < 4; mi++) {
                uint32_t a = cvta_s(&sQ[(kk + (g >> 1) * 8 + (lane & 7)) * 136 +
                                        wm + mi * 16 + (g & 1) * 8]);
                ldsm_x4t(af[mi], a);
            }
            #pragma unroll
            for (int p = 0; p < 2; p++) {
                uint32_t tmp[4];
                uint32_t a = cvta_s(&sK[(kk + ((lane >> 3) & 1) * 8 + (lane & 7)) * 136 +
                                        wn + p * 16 + (lane >> 4) * 8]);
                ldsm_x4t(tmp, a);
                bf_[2 * p][0] = tmp[0]; bf_[2 * p][1] = tmp[1];
                bf_[2 * p + 1][0] = tmp[2]; bf_[2 * p + 1][1] = tmp[3];
            }
            #pragma unroll
            for (int mi = 0; mi < 4; mi++)
                #pragma unroll
                for (int ni = 0; ni < 4; ni++)
                    mma_bf16(acc[mi][ni], af[mi], bf_[ni]);
        }

        // exp -> stg + row-sum partials
        #pragma unroll
        for (int mi = 0; mi < 4; mi++) {
            int r0 = wm + mi * 16 + (lane >> 2);
            #pragma unroll
            for (int ni = 0; ni < 4; ni++) {
                float p0 = __expf(acc[mi][ni][0]);
                float p1 = __expf(acc[mi][ni][1]);
                float p2 = __expf(acc[mi][ni][2]);
                float p3 = __expf(acc[mi][ni][3]);
                rs[mi][0] += p0 + p1;
                rs[mi][1] += p2 + p3;
                int cc = wn + ni * 8 + (lane & 3) * 2;
                __nv_bfloat162 lo = __floats2bfloat162_rn(p0, p1);
                __nv_bfloat162 hi = __floats2bfloat162_rn(p2, p3);
                *reinterpret_cast<__nv_bfloat162*>(&stg[r0 * 136 + cc]) = lo;
                *reinterpret_cast<__nv_bfloat162*>(&stg[(r0 + 8) * 136 + cc]) = hi;
            }
        }
        __syncthreads();   // all MMA reads of K[it&1] done; stg visible

        // prefetch K tile it+2 into buffer (it&1) — safe after the sync above
        if (it + 2 < SC_TILES) {
            const uint32_t koff = (it & 1) ? SC_K1 : SC_K0;
            #pragma unroll
            for (int j = 0; j < 4; j++) {
                int u = tid + j * 256;
                int r = u >> 4, c16 = u & 15;
                cp16cg(sb + koff + (uint32_t)(r * 272 + c16 * 16),
                       &Kb[(size_t)r * T_ + s0g + (it + 2) * 128 + c16 * 8]);
            }
            CP_COMMIT();
        }

        // vectorized P store
        const int sg = s0g + it * 128;
        #pragma unroll
        for (int j = 0; j < 8; j++) {
            int u = tid + j * 256;
            int row = u >> 4, c = (u & 15) * 8;
            *reinterpret_cast<uint4*>(&Pb[(size_t)(t0 + row) * T_ + sg + c]) =
                *reinterpret_cast<const uint4*>(&stg[row * 136 + c]);
        }
    }

    #pragma unroll
    for (int mi = 0; mi < 4; mi++)
        #pragma unroll
        for (int h = 0; h < 2; h++) {
            float v = rs[mi][h];
            v += __shfl_xor_sync(0xffffffffu, v, 1);
            v += __shfl_xor_sync(0xffffffffu, v, 2);
            if ((lane & 3) == 0)
                red[(w & 3) * 128 + wm + mi * 16 + h * 8 + (lane >> 2)] = v;
        }
    __syncthreads();
    if (tid < 128) {
        float tot = red[tid] + red[128 + tid] + red[256 + tid] + red[384 + tid];
        partial[((size_t)b * 4 + blockIdx.x) * T_ + t0 + tid] = tot;
    }
}

// ---------------------------------------------------------------------------
// Output GEMM (round-12 winner): 128x128 tile, 128 threads = 4 warps (2m x 2n),
// warp tile 64x64, cp.async(.cg) double-buffered, fused inv prologue.
// ---------------------------------------------------------------------------
#define OA0 0u
#define OA1 18432u
#define OB0 36864u
#define OB1 55296u
#define OINV 73728u
#define OUT_SMEM 74240u

__device__ __forceinline__ void out_issue_chunk(const bf16* Vb, const bf16* Pb,
                                                int m0, int n0, int kc,
                                                uint32_t sb, int buf, int tid)
{
    const uint32_t aoff = buf ? OA1 : OA0;
    const uint32_t boff = buf ? OB1 : OB0;
    #pragma unroll
    for (int j = 0; j < 8; j++) {
        int u = tid + j * 128;
        int row = u >> 3, c16 = u & 7;
        cp16cg(sb + aoff + (uint32_t)(row * 144 + c16 * 16),
               &Vb[(size_t)(m0 + row) * T_ + kc + c16 * 8]);
    }
    #pragma unroll
    for (int j = 0; j < 8; j++) {
        int u = tid + j * 128;
        int row = u >> 3, c16 = u & 7;
        cp16cg(sb + boff + (uint32_t)(row * 144 + c16 * 16),
               &Pb[(size_t)(n0 + row) * T_ + kc + c16 * 8]);
    }
    CP_COMMIT();
}

__global__ void __launch_bounds__(128, 2)
out_mma5(const bf16* __restrict__ QKV, const bf16* __restrict__ P,
         const float* __restrict__ rsum, const float* __restrict__ x,
         const float* __restrict__ gamma, float* __restrict__ O)
{
    extern __shared__ __align__(128) char smem[];
    const uint32_t sb = cvta_s(smem);
    float* sInv = reinterpret_cast<float*>(smem + OINV);

    const int b  = blockIdx.z;
    const int n0 = blockIdx.x * 128;   // t
    const int m0 = blockIdx.y * 128;   // c
    const bf16* Vb = QKV + (size_t)b * MQKV * T_ + (size_t)(2 * CQ_) * T_;
    const bf16* Pb = P + (size_t)b * T_ * T_;

    const int tid  = threadIdx.x;
    const int lane = tid & 31;
    const int w    = tid >> 5;
    const int wm   = (w >> 1) * 64;
    const int wn   = (w & 1) * 64;

    // fused inv over the 4 s-slice partials
    {
        const float* p = rsum + (size_t)b * 4 * T_ + n0 + tid;
        float s = 0.0f;
        #pragma unroll
        for (int j = 0; j < 4; j++) s += p[j * T_];
        sInv[tid] = 1.0f / s;
    }

    float acc[4][8][4] = {};

    out_issue_chunk(Vb, Pb, m0, n0, 0,  sb, 0, tid);
    out_issue_chunk(Vb, Pb, m0, n0, 64, sb, 1, tid);

    #pragma unroll 1
    for (int ch = 0; ch < 32; ch++) {
        const int buf = ch & 1;
        if (ch < 31) { CP_WAIT(1); } else { CP_WAIT(0); }
        __syncthreads();

        const bf16* sA = reinterpret_cast<const bf16*>(smem + (buf ? OA1 : OA0));
        const bf16* sB = reinterpret_cast<const bf16*>(smem + (buf ? OB1 : OB0));

        #pragma unroll
        for (int kk = 0; kk < 64; kk += 16) {
            uint32_t af[4][4], bf_[8][2];
            #pragma unroll
            for (int mi = 0; mi < 4; mi++) {
                uint32_t a = cvta_s(&sA[(wm + mi * 16 + (lane & 15)) * 72 + kk + (lane >> 4) * 8]);
                ldsm_x4(af[mi], a);
            }
            #pragma unroll
            for (int p = 0; p < 4; p++) {
                uint32_t tmp[4];
                uint32_t a = cvta_s(&sB[(wn + p * 16 + (lane >> 4) * 8 + (lane & 7)) * 72 +
                                        kk + ((lane >> 3) & 1) * 8]);
                ldsm_x4(tmp, a);
                bf_[2 * p][0] = tmp[0]; bf_[2 * p][1] = tmp[1];
                bf_[2 * p + 1][0] = tmp[2]; bf_[2 * p + 1][1] = tmp[3];
            }
            #pragma unroll
            for (int mi = 0; mi < 4; mi++)
                #pragma unroll
                for (int ni = 0; ni < 8; ni++)
                    mma_bf16(acc[mi][ni], af[mi], bf_[ni]);
        }
        __syncthreads();

        if (ch + 2 < 32)
            out_issue_chunk(Vb, Pb, m0, n0, (ch + 2) * 64, sb, buf, tid);
    }

    const float g = gamma[0];
    #pragma unroll
    for (int mi = 0; mi < 4; mi++) {
        int grow = m0 + wm + mi * 16 + (lane >> 2);
        #pragma unroll
        for (int ni = 0; ni < 8; ni++) {
            int lc = wn + ni * 8 + (lane & 3) * 2;
            int gcol = n0 + lc;
            float2 iv = *reinterpret_cast<const float2*>(&sInv[lc]);
            size_t i0 = (size_t)b * C_ * T_ + (size_t)grow * T_ + gcol;
            size_t i1 = (size_t)b * C_ * T_ + (size_t)(grow + 8) * T_ + gcol;
            float2 x0 = *reinterpret_cast<const float2*>(&x[i0]);
            float2 x1 = *reinterpret_cast<const float2*>(&x[i1]);
            *reinterpret_cast<float2*>(&O[i0]) =
                make_float2(g * acc[mi][ni][0] * iv.x + x0.x, g * acc[mi][ni][1] * iv.y + x0.y);
            *reinterpret_cast<float2*>(&O[i1]) =
                make_float2(g * acc[mi][ni][2] * iv.x + x1.x, g * acc[mi][ni][3] * iv.y + x1.y);
        }
    }
}

// ---------------------------------------------------------------------------
// Launch (single stream — R12 structure)
// ---------------------------------------------------------------------------
extern "C" void kernel_launch(void* const* d_in, const int* in_sizes, int n_in,
                              void* d_out, int out_size)
{
    const float* x     = (const float*)d_in[0];
    const float* wq    = (const float*)d_in[1];
    const float* bq    = (const float*)d_in[2];
    const float* wk    = (const float*)d_in[3];
    const float* bk    = (const float*)d_in[4];
    const float* wv    = (const float*)d_in[5];
    const float* bv    = (const float*)d_in[6];
    const float* gamma = (const float*)d_in[7];
    float* out = (float*)d_out;

    bf16 *xb, *wall, *qkv, *pb;
    float *ball, *rs;
    cudaGetSymbolAddress((void**)&xb,   g_xb);
    cudaGetSymbolAddress((void**)&wall, g_wall);
    cudaGetSymbolAddress((void**)&ball, g_ball);
    cudaGetSymbolAddress((void**)&qkv,  g_qkv);
    cudaGetSymbolAddress((void**)&pb,   g_p);
    cudaGetSymbolAddress((void**)&rs,   g_rs);

    cudaFuncSetAttribute(proj_stk,   cudaFuncAttributeMaxDynamicSharedMemorySize, PJ_SMEM);
    cudaFuncSetAttribute(score_exp6, cudaFuncAttributeMaxDynamicSharedMemorySize, SC_SMEM);
    cudaFuncSetAttribute(out_mma5,   cudaFuncAttributeMaxDynamicSharedMemorySize, OUT_SMEM);

    f2b_all<<<(NTOT + 255) / 256, 256>>>(x, xb, wq, wk, wv, wall, bq, bk, bv, ball);

    proj_stk<<<dim3(T_ / 128, MQKV / 128, B_), 256, PJ_SMEM>>>(wall, ball, xb, qkv);

    score_exp6<<<dim3(T_ / 512, T_ / 128, B_), 256, SC_SMEM>>>(qkv, pb, rs);

    out_mma5<<<dim3(T_ / 128, C_ / 128, B_), 128, OUT_SMEM>>>(qkv, pb, rs, x, gamma, out);
}